// round 6
// baseline (speedup 1.0000x reference)
#include <cuda_runtime.h>
#include <math.h>

#define D       128
#define KEEP    10
#define NCHUNK  50
#define TM      128
#define TN      64
#define TK      16
#define MAXM    2048
#define MAXN    100000

// ---- device scratch (static globals: the sanctioned no-alloc workaround) ----
__device__ float g_c[MAXN];                          // ||X_j||^2 - w[j]
__device__ float g_pv[MAXM * NCHUNK * KEEP];         // per-chunk top-10 scores
__device__ int   g_pi[MAXM * NCHUNK * KEEP];         // per-chunk top-10 indices

__device__ __forceinline__ float inf_f() { return __int_as_float(0x7f800000); }

// packed fp32x2 FMA (Blackwell FFMA2 — only reachable via PTX)
#define FMA_F32X2(acc, a, b) \
    asm("fma.rn.f32x2 %0, %1, %2, %0;" : "+l"(acc) : "l"(a), "l"(b))

__device__ __forceinline__ unsigned long long pack2(float lo, float hi) {
    return ((unsigned long long)__float_as_uint(hi) << 32) | (unsigned long long)__float_as_uint(lo);
}

// ============================================================================
// Kernel 1: c[j] = ||X_j||^2 - w[j]   (one warp per row)
// ============================================================================
__global__ void prep_kernel(const float* __restrict__ X, const float* __restrict__ w, int n) {
    int gwarp = (blockIdx.x * blockDim.x + threadIdx.x) >> 5;
    int lane  = threadIdx.x & 31;
    if (gwarp >= n) return;
    const float4* row = (const float4*)(X + (size_t)gwarp * D);
    float4 v = row[lane];                 // D/4 = 32 float4 -> one per lane
    float s = v.x * v.x + v.y * v.y + v.z * v.z + v.w * v.w;
    #pragma unroll
    for (int o = 16; o > 0; o >>= 1) s += __shfl_xor_sync(0xffffffffu, s, o);
    if (lane == 0) g_c[gwarp] = s - w[gwarp];
}

// ============================================================================
// Kernel 2: fused 128q x 64cand tiled GEMM (f32x2) + streaming top-10
//   grid = (NCHUNK, m/TM), block = 256
// ============================================================================
__global__ void __launch_bounds__(256)
score_topk_kernel(const float* __restrict__ Q, const float* __restrict__ X,
                  int m, int n)
{
    __shared__ unsigned long long As2[TK / 2][TM];   // k-pairs packed, 8KB
    __shared__ unsigned long long Bs2[TK / 2][TN];   // 4KB
    __shared__ float Sc[TM][TN + 1];                 // raw dots, 33.3KB (padded)
    __shared__ float Cs[TN];                         // c[j] for this cand tile

    const int tid   = threadIdx.x;
    const int chunk = blockIdx.x;
    const int qb    = blockIdx.y * TM;

    const int per = (n + NCHUNK - 1) / NCHUNK;       // 2000
    const int j0  = chunk * per;
    const int j1  = min(n, j0 + per);

    const int tx    = tid & 7;        // 8 groups of candidates
    const int ty    = tid >> 3;       // 32 groups of queries
    const int qrow0 = ty * 4;         // 4 queries per thread
    const int col0  = tx * 8;         // 8 candidates per thread

    // per-query top-10 (sorted ascending; tv[9] = current threshold)
    float tv[KEEP];
    int   ti[KEEP];
    #pragma unroll
    for (int t = 0; t < KEEP; t++) { tv[t] = inf_f(); ti[t] = -1; }

    #pragma unroll 1
    for (int jb = j0; jb < j1; jb += TN) {
        unsigned long long acc[4][8];
        #pragma unroll
        for (int i = 0; i < 4; i++)
            #pragma unroll
            for (int j = 0; j < 8; j++) acc[i][j] = 0ull;

        #pragma unroll 1
        for (int kk = 0; kk < D; kk += TK) {
            __syncthreads();   // previous compute done; on kk==0: previous scan done
            if (kk == 0 && tid < TN) {
                int j = jb + tid;
                Cs[tid] = (j < j1) ? g_c[j] : inf_f();
            }
            // load A tile: TM x TK floats -> 2 float4 per thread, pack k-pairs
            #pragma unroll
            for (int l = 0; l < 2; l++) {
                int slot = l * 256 + tid;           // 0..511
                int mrow = slot >> 2;               // 0..127
                int c4   = (slot & 3) << 2;         // 0,4,8,12
                int gq   = min(qb + mrow, m - 1);
                float4 v = *(const float4*)(Q + (size_t)gq * D + kk + c4);
                As2[(c4 >> 1) + 0][mrow] = pack2(v.x, v.y);
                As2[(c4 >> 1) + 1][mrow] = pack2(v.z, v.w);
            }
            // load B tile: TN x TK floats -> 1 float4 per thread
            {
                int jrow = tid >> 2;                // 0..63
                int c4   = (tid & 3) << 2;          // 0,4,8,12
                int gj   = min(jb + jrow, n - 1);
                float4 v = *(const float4*)(X + (size_t)gj * D + kk + c4);
                Bs2[(c4 >> 1) + 0][jrow] = pack2(v.x, v.y);
                Bs2[(c4 >> 1) + 1][jrow] = pack2(v.z, v.w);
            }
            __syncthreads();

            #pragma unroll
            for (int kp = 0; kp < TK / 2; kp++) {
                ulonglong2 a01 = *(const ulonglong2*)&As2[kp][qrow0];
                ulonglong2 a23 = *(const ulonglong2*)&As2[kp][qrow0 + 2];
                ulonglong2 b01 = *(const ulonglong2*)&Bs2[kp][col0];
                ulonglong2 b23 = *(const ulonglong2*)&Bs2[kp][col0 + 2];
                ulonglong2 b45 = *(const ulonglong2*)&Bs2[kp][col0 + 4];
                ulonglong2 b67 = *(const ulonglong2*)&Bs2[kp][col0 + 6];
                unsigned long long a[4] = { a01.x, a01.y, a23.x, a23.y };
                unsigned long long b[8] = { b01.x, b01.y, b23.x, b23.y,
                                            b45.x, b45.y, b67.x, b67.y };
                #pragma unroll
                for (int i = 0; i < 4; i++)
                    #pragma unroll
                    for (int j = 0; j < 8; j++)
                        FMA_F32X2(acc[i][j], a[i], b[j]);
            }
        }

        // stage dot products to smem
        #pragma unroll
        for (int i = 0; i < 4; i++)
            #pragma unroll
            for (int j = 0; j < 8; j++) {
                unsigned long long v = acc[i][j];
                float lo = __uint_as_float((unsigned)v);
                float hi = __uint_as_float((unsigned)(v >> 32));
                Sc[qrow0 + i][col0 + j] = lo + hi;
            }
        __syncthreads();

        // stream-scan: one thread per query row
        if (tid < TM) {
            #pragma unroll 4
            for (int jj = 0; jj < TN; jj++) {
                float s = Cs[jj] - 2.0f * Sc[tid][jj];     // = x2 - w - 2 q.x
                if (s < tv[KEEP - 1]) {
                    tv[KEEP - 1] = s;
                    ti[KEEP - 1] = jb + jj;
                    #pragma unroll
                    for (int t = KEEP - 1; t > 0; --t) {
                        if (tv[t] < tv[t - 1]) {
                            float fv = tv[t]; tv[t] = tv[t - 1]; tv[t - 1] = fv;
                            int   iv = ti[t]; ti[t] = ti[t - 1]; ti[t - 1] = iv;
                        }
                    }
                }
            }
        }
    }

    if (tid < TM && (qb + tid) < m) {
        int base = ((qb + tid) * NCHUNK + chunk) * KEEP;
        #pragma unroll
        for (int t = 0; t < KEEP; t++) {
            g_pv[base + t] = tv[t];
            g_pi[base + t] = ti[t];
        }
    }
}

// ============================================================================
// Kernel 3: merge 50x10 partial lists -> exact top-10 -> rescore -> max act
//   grid = m, block = 128 (= D)
// ============================================================================
__global__ void __launch_bounds__(128)
merge_kernel(const float* __restrict__ Q, const float* __restrict__ X,
             const float* __restrict__ w, float* __restrict__ out, int n)
{
    __shared__ float sv[NCHUNK * KEEP];
    __shared__ int   si[NCHUNK * KEEP];
    __shared__ float qs[D];
    __shared__ float rv[128];
    __shared__ int   ri[128];
    __shared__ int   s_sel;

    const int q   = blockIdx.x;
    const int tid = threadIdx.x;

    for (int t = tid; t < NCHUNK * KEEP; t += 128) {
        sv[t] = g_pv[q * NCHUNK * KEEP + t];
        si[t] = g_pi[q * NCHUNK * KEEP + t];
    }
    qs[tid] = Q[(size_t)q * D + tid];
    __syncthreads();

    float best = -inf_f();

    for (int r = 0; r < KEEP; r++) {
        // block argmin over the 500 candidates
        float mv = inf_f();
        int   mi = -1;
        for (int t = tid; t < NCHUNK * KEEP; t += 128)
            if (sv[t] < mv) { mv = sv[t]; mi = t; }
        rv[tid] = mv; ri[tid] = mi;
        __syncthreads();
        #pragma unroll
        for (int s = 64; s > 0; s >>= 1) {
            if (tid < s && rv[tid + s] < rv[tid]) { rv[tid] = rv[tid + s]; ri[tid] = ri[tid + s]; }
            __syncthreads();
        }
        if (tid == 0) {
            int sel = ri[0];
            s_sel = (sel >= 0) ? si[sel] : -1;
            if (sel >= 0) sv[sel] = inf_f();        // remove from pool
        }
        __syncthreads();
        int idx = s_sel;

        // exact squared distance, block-reduced
        float p = 0.0f;
        if (idx >= 0) {
            float dfe = X[(size_t)idx * D + tid] - qs[tid];
            p = dfe * dfe;
        }
        rv[tid] = p;
        __syncthreads();
        #pragma unroll
        for (int s = 64; s > 0; s >>= 1) {
            if (tid < s) rv[tid] += rv[tid + s];
            __syncthreads();
        }
        if (tid == 0 && idx >= 0) {
            float act = w[idx] - sqrtf(rv[0]);      // K_CONST = 1
            best = fmaxf(best, act);
        }
        __syncthreads();
    }

    if (tid == 0) out[q] = best;
}

// ============================================================================
// launch
// ============================================================================
extern "C" void kernel_launch(void* const* d_in, const int* in_sizes, int n_in,
                              void* d_out, int out_size)
{
    const float* Xt = (const float*)d_in[0];   // (m, d) queries
    const float* X  = (const float*)d_in[1];   // (n, d) points
    const float* w  = (const float*)d_in[2];   // (n, 1)
    float* out = (float*)d_out;                // (m,)

    int n = in_sizes[2];                       // 100000
    int d = in_sizes[1] / n;                   // 128
    int m = in_sizes[0] / d;                   // 2048
    (void)n_in; (void)out_size; (void)d;

    // K1: per-row norms minus w  (warp per row, 8 rows per 256-thread block)
    prep_kernel<<<(n + 7) / 8, 256>>>(X, w, n);

    // K2: fused GEMM + per-chunk top-10
    dim3 grid(NCHUNK, (m + TM - 1) / TM);
    score_topk_kernel<<<grid, 256>>>(Xt, X, m, n);

    // K3: merge + exact rescore + max
    merge_kernel<<<m, 128>>>(Xt, X, w, out, n);
}

// round 11
// speedup vs baseline: 5.2512x; 5.2512x over previous
#include <cuda_runtime.h>
#include <cuda_bf16.h>
#include <math.h>
#include <stdint.h>

#define D       128
#define KEEP    10
#define NCH     9
#define KC      384            // split-K: [hi|lo|hi] . [hi|hi|lo]
#define MAXM    2048
#define MAXN    100000

// ---------------- device scratch (static globals; no allocs) ----------------
__device__ float          g_c[MAXN];                       // ||X_j||^2 - w[j]
__device__ __nv_bfloat16  g_xc[(size_t)MAXN * KC];         // X split, [hi|hi|lo]
__device__ __nv_bfloat16  g_qc[(size_t)MAXM * KC];         // Q split, [hi|lo|hi]
__device__ float          g_pv[MAXM * NCH * KEEP];
__device__ int            g_pi[MAXM * NCH * KEEP];

__device__ __forceinline__ float inf_f() { return __int_as_float(0x7f800000); }

// ---------------- PTX helpers ----------------
__device__ __forceinline__ uint32_t smem_u32(const void* p) {
    uint32_t a;
    asm("{ .reg .u64 t; cvta.to.shared.u64 t, %1; cvt.u32.u64 %0, t; }" : "=r"(a) : "l"(p));
    return a;
}
#define CP_COMMIT() asm volatile("cp.async.commit_group;" ::: "memory")
#define CP_WAIT0()  asm volatile("cp.async.wait_group 0;" ::: "memory")
__device__ __forceinline__ void cp16(uint32_t dst, const void* src) {
    asm volatile("cp.async.cg.shared.global [%0], [%1], 16;" :: "r"(dst), "l"(src) : "memory");
}
#define LDSM_X4(r0, r1, r2, r3, addr) \
    asm volatile("ldmatrix.sync.aligned.m8n8.x4.shared.b16 {%0,%1,%2,%3}, [%4];" \
                 : "=r"(r0), "=r"(r1), "=r"(r2), "=r"(r3) : "r"(addr))
#define MMA16816(d, a, b0, b1) \
    asm volatile("mma.sync.aligned.m16n8k16.row.col.f32.bf16.bf16.f32 " \
                 "{%0,%1,%2,%3}, {%4,%5,%6,%7}, {%8,%9}, {%0,%1,%2,%3};" \
                 : "+f"((d)[0]), "+f"((d)[1]), "+f"((d)[2]), "+f"((d)[3]) \
                 : "r"((a)[0]), "r"((a)[1]), "r"((a)[2]), "r"((a)[3]), \
                   "r"(b0), "r"(b1))

// ---------------- SMEM layout (dynamic) ----------------
#define SM_A      0            // 6 slabs x [128 rows x 128B] SW128 = 96KB
#define SM_B0     98304        // [128 x 128B] chunk = 16KB
#define SM_B1     114688
#define SM_SC     131072       // 128 x 132 floats = 67584B
#define SM_CS     198656       // 128 floats
#define SMEM_TOTAL 199168

// ============================================================================
// Kernel 0a/0b: fp32 -> bf16 split-concat
// ============================================================================
__global__ void convert_x_kernel(const float* __restrict__ X, int n) {
    size_t i = (size_t)blockIdx.x * 256 + threadIdx.x;
    if (i >= (size_t)n * D) return;
    int j = (int)(i >> 7), c = (int)(i & 127);
    float x = X[i];
    __nv_bfloat16 hi = __float2bfloat16(x);
    __nv_bfloat16 lo = __float2bfloat16(x - __bfloat162float(hi));
    size_t b = (size_t)j * KC;
    g_xc[b + c] = hi; g_xc[b + 128 + c] = hi; g_xc[b + 256 + c] = lo;   // [hi|hi|lo]
}
__global__ void convert_q_kernel(const float* __restrict__ Q, int m) {
    size_t i = (size_t)blockIdx.x * 256 + threadIdx.x;
    if (i >= (size_t)m * D) return;
    int j = (int)(i >> 7), c = (int)(i & 127);
    float x = Q[i];
    __nv_bfloat16 hi = __float2bfloat16(x);
    __nv_bfloat16 lo = __float2bfloat16(x - __bfloat162float(hi));
    size_t b = (size_t)j * KC;
    g_qc[b + c] = hi; g_qc[b + 128 + c] = lo; g_qc[b + 256 + c] = hi;   // [hi|lo|hi]
}

// ============================================================================
// Kernel 1: c[j] = ||X_j||^2 - w[j]
// ============================================================================
__global__ void prep_kernel(const float* __restrict__ X, const float* __restrict__ w, int n) {
    int gw = (blockIdx.x * blockDim.x + threadIdx.x) >> 5;
    int lane = threadIdx.x & 31;
    if (gw >= n) return;
    float4 v = ((const float4*)(X + (size_t)gw * D))[lane];
    float s = v.x * v.x + v.y * v.y + v.z * v.z + v.w * v.w;
    #pragma unroll
    for (int o = 16; o > 0; o >>= 1) s += __shfl_xor_sync(0xffffffffu, s, o);
    if (lane == 0) g_c[gw] = s - w[gw];
}

// ============================================================================
// Kernel 2: HMMA (mma.sync bf16) GEMM 128q x 128c x 384 + streaming top-10
//   grid = (NCH, m/128), block = 256 (8 warps, 4x2 warp grid)
// ============================================================================
__device__ __forceinline__ void issue_B(uint32_t dst, int jt0, int kc, int j1, int tid) {
    #pragma unroll
    for (int i = 0; i < 4; i++) {
        int seg = tid + 256 * i;            // 0..1023
        int r = seg >> 3, g = seg & 7;
        int j = min(jt0 + r, j1 - 1);
        const void* src = g_xc + (size_t)j * KC + kc * 64 + g * 8;
        uint32_t off = (uint32_t)(r * 128 + g * 16) ^ ((uint32_t)(r & 7) << 4);
        cp16(dst + off, src);
    }
    CP_COMMIT();
}

__global__ void __launch_bounds__(256, 1)
score_kernel(int m, int n)
{
    extern __shared__ char smem[];
    const uint32_t sb = smem_u32(smem);
    const int tid  = threadIdx.x;
    const int lane = tid & 31;
    const int w    = tid >> 5;
    const int qw   = w >> 1;            // 0..3
    const int cw   = w & 1;             // 0..1
    const int chunk = blockIdx.x, qb = blockIdx.y * 128;

    const int per = (n + NCH - 1) / NCH;
    const int j0  = chunk * per;
    const int j1  = min(n, j0 + per);
    const int ntiles = (j1 - j0 + 127) / 128;

    float* ScF = (float*)(smem + SM_SC);
    float* cs  = (float*)(smem + SM_CS);

    // ---- load resident A: 128 rows x 384 bf16 into 6 SW128 slabs ----
    #pragma unroll
    for (int i = 0; i < 24; i++) {
        int seg = tid + 256 * i;            // 0..6143
        int row = seg / 48, s = seg % 48;
        int gq = min(qb + row, m - 1);
        const void* src = g_qc + (size_t)gq * KC + s * 8;
        uint32_t off = (uint32_t)((s >> 3) * 16384)
                     + (((uint32_t)(row * 128 + (s & 7) * 16)) ^ ((uint32_t)(row & 7) << 4));
        cp16(sb + SM_A + off, src);
    }
    CP_COMMIT();
    issue_B(sb + SM_B0, j0, 0, j1, tid);

    // per-lane ldmatrix base offsets (swizzle masks depend only on row)
    // A: row = qw*32 + mi*16 + (lane&15); khalf = lane>>4
    uint32_t arow0 = (uint32_t)(qw * 32 + (lane & 15));
    uint32_t abase[2], amask[2];
    #pragma unroll
    for (int mi = 0; mi < 2; mi++) {
        uint32_t r = arow0 + mi * 16;
        abase[mi] = r * 128 + ((uint32_t)(lane >> 4) << 4);
        amask[mi] = (r & 7) << 4;
    }
    // B: n = cw*64 + ni*16 + (lane&7) + ((lane>>4)<<3); khalf = (lane>>3)&1
    uint32_t bbaseL[4], bmaskL[4];
    #pragma unroll
    for (int ni = 0; ni < 4; ni++) {
        uint32_t nr = (uint32_t)(cw * 64 + ni * 16 + (lane & 7) + ((lane >> 4) << 3));
        bbaseL[ni] = nr * 128 + (((uint32_t)(lane >> 3) & 1) << 4);
        bmaskL[ni] = (nr & 7) << 4;
    }

    float tv[KEEP]; int ti[KEEP];
    #pragma unroll
    for (int k = 0; k < KEEP; k++) { tv[k] = inf_f(); ti[k] = -1; }

    const uint32_t bbuf[2] = { sb + SM_B0, sb + SM_B1 };
    const int q  = tid >> 1;            // scan query (2 threads/query)
    const int hf = tid & 1;

    for (int t = 0; t < ntiles; t++) {
        int jt0 = j0 + t * 128;

        float acc[2][8][4];
        #pragma unroll
        for (int mi = 0; mi < 2; mi++)
            #pragma unroll
            for (int nj = 0; nj < 8; nj++)
                #pragma unroll
                for (int e = 0; e < 4; e++) acc[mi][nj][e] = 0.0f;

        #pragma unroll 1
        for (int kc = 0; kc < 6; kc++) {
            CP_WAIT0();
            __syncthreads();
            if (kc == 0 && tid < 128) {
                int j = jt0 + tid;
                cs[tid] = (j < j1) ? g_c[j] : inf_f();
            }
            if (kc < 5)                 issue_B(bbuf[(kc + 1) & 1], jt0, kc + 1, j1, tid);
            else if (t + 1 < ntiles)    issue_B(sb + SM_B0, jt0 + 128, 0, j1, tid);

            const uint32_t aslab = sb + SM_A + kc * 16384;
            const uint32_t bcur  = bbuf[kc & 1];
            #pragma unroll
            for (int ks = 0; ks < 4; ks++) {
                const uint32_t kb = (uint32_t)(ks * 32);
                uint32_t a0[4], a1[4];
                LDSM_X4(a0[0], a0[1], a0[2], a0[3], aslab + ((abase[0] + kb) ^ amask[0]));
                LDSM_X4(a1[0], a1[1], a1[2], a1[3], aslab + ((abase[1] + kb) ^ amask[1]));
                #pragma unroll
                for (int ni = 0; ni < 4; ni++) {
                    uint32_t b[4];
                    LDSM_X4(b[0], b[1], b[2], b[3], bcur + ((bbaseL[ni] + kb) ^ bmaskL[ni]));
                    MMA16816(acc[0][2 * ni],     a0, b[0], b[1]);
                    MMA16816(acc[0][2 * ni + 1], a0, b[2], b[3]);
                    MMA16816(acc[1][2 * ni],     a1, b[0], b[1]);
                    MMA16816(acc[1][2 * ni + 1], a1, b[2], b[3]);
                }
            }
        }

        // ---- epilogue: stage scores to smem (stride 132) ----
        {
            int r0 = qw * 32 + (lane >> 2);
            int c0 = cw * 64 + (lane & 3) * 2;
            #pragma unroll
            for (int mi = 0; mi < 2; mi++)
                #pragma unroll
                for (int nj = 0; nj < 8; nj++) {
                    int row = r0 + mi * 16;
                    int col = c0 + nj * 8;
                    ScF[row * 132 + col]           = acc[mi][nj][0];
                    ScF[row * 132 + col + 1]       = acc[mi][nj][1];
                    ScF[(row + 8) * 132 + col]     = acc[mi][nj][2];
                    ScF[(row + 8) * 132 + col + 1] = acc[mi][nj][3];
                }
        }
        __syncthreads();

        // ---- scan: 2 threads per query, 64 cols each, rotation-skewed ----
        {
            const float* srow = ScF + q * 132;
            const int rot = 2 * q + hf;
            #pragma unroll 4
            for (int jj = 0; jj < 64; jj++) {
                int col = hf * 64 + ((jj + rot) & 63);
                float s = cs[col] - 2.0f * srow[col];
                if (s < tv[KEEP - 1]) {
                    tv[KEEP - 1] = s; ti[KEEP - 1] = jt0 + col;
                    #pragma unroll
                    for (int k = KEEP - 1; k > 0; --k) {
                        if (tv[k] < tv[k - 1]) {
                            float fv = tv[k]; tv[k] = tv[k - 1]; tv[k - 1] = fv;
                            int   iv = ti[k]; ti[k] = ti[k - 1]; ti[k - 1] = iv;
                        }
                    }
                }
            }
        }
        // next iteration's CP_WAIT0 + __syncthreads orders everything
    }

    // ---- merge the two per-query half-lists, write partials ----
    __syncthreads();
    float* fvs = (float*)(smem + SM_SC);
    int*   ivs = (int*)(smem + SM_SC + 256 * KEEP * 4);
    #pragma unroll
    for (int k = 0; k < KEEP; k++) { fvs[tid * KEEP + k] = tv[k]; ivs[tid * KEEP + k] = ti[k]; }
    __syncthreads();
    if (tid < 128) {
        const float* av = fvs + (2 * tid) * KEEP;
        const int*   ai = ivs + (2 * tid) * KEEP;
        const float* bv = fvs + (2 * tid + 1) * KEEP;
        const int*   bi = ivs + (2 * tid + 1) * KEEP;
        int base = ((qb + tid) * NCH + chunk) * KEEP;
        int x = 0, y = 0;
        #pragma unroll
        for (int k = 0; k < KEEP; k++) {
            float a = av[x], b = bv[y];
            bool ta = (a <= b);
            g_pv[base + k] = ta ? a : b;
            g_pi[base + k] = ta ? ai[x] : bi[y];
            if (ta) x++; else y++;
        }
    }
}

// ============================================================================
// Kernel 3: merge NCH x 10 partials -> exact top-10 -> rescore -> max act
// ============================================================================
__global__ void __launch_bounds__(128)
merge_kernel(const float* __restrict__ Q, const float* __restrict__ X,
             const float* __restrict__ w, float* __restrict__ out)
{
    __shared__ float sv[NCH * KEEP];
    __shared__ int   si[NCH * KEEP];
    __shared__ float qs[D];
    __shared__ float rv[128];
    __shared__ int   ri[128];
    __shared__ int   s_sel;

    const int q = blockIdx.x, tid = threadIdx.x;

    for (int t = tid; t < NCH * KEEP; t += 128) {
        sv[t] = g_pv[q * NCH * KEEP + t];
        si[t] = g_pi[q * NCH * KEEP + t];
    }
    qs[tid] = Q[(size_t)q * D + tid];
    __syncthreads();

    float best = -inf_f();
    for (int r = 0; r < KEEP; r++) {
        float mv = inf_f(); int mi = -1;
        for (int t = tid; t < NCH * KEEP; t += 128)
            if (sv[t] < mv) { mv = sv[t]; mi = t; }
        rv[tid] = mv; ri[tid] = mi;
        __syncthreads();
        #pragma unroll
        for (int s = 64; s > 0; s >>= 1) {
            if (tid < s && rv[tid + s] < rv[tid]) { rv[tid] = rv[tid + s]; ri[tid] = ri[tid + s]; }
            __syncthreads();
        }
        if (tid == 0) {
            int sel = ri[0];
            s_sel = (sel >= 0 && rv[0] < inf_f()) ? si[sel] : -1;
            if (sel >= 0) sv[sel] = inf_f();
        }
        __syncthreads();
        int idx = s_sel;

        float p = 0.0f;
        if (idx >= 0) {
            float df = X[(size_t)idx * D + tid] - qs[tid];
            p = df * df;
        }
        rv[tid] = p;
        __syncthreads();
        #pragma unroll
        for (int s = 64; s > 0; s >>= 1) {
            if (tid < s) rv[tid] += rv[tid + s];
            __syncthreads();
        }
        if (tid == 0 && idx >= 0) best = fmaxf(best, w[idx] - sqrtf(rv[0]));
        __syncthreads();
    }
    if (tid == 0) out[q] = best;
}

// ============================================================================
// launch
// ============================================================================
extern "C" void kernel_launch(void* const* d_in, const int* in_sizes, int n_in,
                              void* d_out, int out_size)
{
    const float* Xt = (const float*)d_in[0];   // (m, d) queries
    const float* X  = (const float*)d_in[1];   // (n, d) points
    const float* w  = (const float*)d_in[2];   // (n, 1)
    float* out = (float*)d_out;

    int n = in_sizes[2];
    int d = in_sizes[1] / n;
    int m = in_sizes[0] / d;
    (void)n_in; (void)out_size;

    cudaFuncSetAttribute(score_kernel, cudaFuncAttributeMaxDynamicSharedMemorySize, SMEM_TOTAL);

    // 0: bf16 split-concat of X and Q
    convert_x_kernel<<<(int)(((size_t)n * D + 255) / 256), 256>>>(X, n);
    convert_q_kernel<<<(int)(((size_t)m * D + 255) / 256), 256>>>(Xt, m);

    // 1: c[j] = ||X_j||^2 - w[j]
    prep_kernel<<<(n + 7) / 8, 256>>>(X, w, n);

    // 2: HMMA GEMM + per-chunk top-10
    dim3 grid(NCH, (m + 127) / 128);
    score_kernel<<<grid, 256, SMEM_TOTAL>>>(m, n);

    // 3: merge + exact rescore + max
    merge_kernel<<<m, 128>>>(Xt, X, w, out);
}

// round 12
// speedup vs baseline: 5.5644x; 1.0596x over previous
#include <cuda_runtime.h>
#include <cuda_bf16.h>
#include <math.h>
#include <stdint.h>

#define D       128
#define KEEP    10
#define NCH     9
#define KC      384            // split-K: [hi|lo|hi] . [hi|hi|lo]
#define MAXM    2048
#define MAXN    100000

// ---------------- device scratch (static globals; no allocs) ----------------
__device__ float          g_c[MAXN];                       // ||X_j||^2 - w[j]
__device__ __nv_bfloat16  g_xc[(size_t)MAXN * KC];         // X split, [hi|hi|lo]
__device__ __nv_bfloat16  g_qc[(size_t)MAXM * KC];         // Q split, [hi|lo|hi]
__device__ float          g_pv[MAXM * NCH * KEEP];
__device__ int            g_pi[MAXM * NCH * KEEP];

__device__ __forceinline__ float inf_f() { return __int_as_float(0x7f800000); }

// ---------------- PTX helpers ----------------
__device__ __forceinline__ uint32_t smem_u32(const void* p) {
    uint32_t a;
    asm("{ .reg .u64 t; cvta.to.shared.u64 t, %1; cvt.u32.u64 %0, t; }" : "=r"(a) : "l"(p));
    return a;
}
#define CP_COMMIT() asm volatile("cp.async.commit_group;" ::: "memory")
#define CP_WAIT0()  asm volatile("cp.async.wait_group 0;" ::: "memory")
__device__ __forceinline__ void cp16(uint32_t dst, const void* src) {
    asm volatile("cp.async.cg.shared.global [%0], [%1], 16;" :: "r"(dst), "l"(src) : "memory");
}
#define LDSM_X4(r0, r1, r2, r3, addr) \
    asm volatile("ldmatrix.sync.aligned.m8n8.x4.shared.b16 {%0,%1,%2,%3}, [%4];" \
                 : "=r"(r0), "=r"(r1), "=r"(r2), "=r"(r3) : "r"(addr))
#define MMA16816(d, a, b0, b1) \
    asm volatile("mma.sync.aligned.m16n8k16.row.col.f32.bf16.bf16.f32 " \
                 "{%0,%1,%2,%3}, {%4,%5,%6,%7}, {%8,%9}, {%0,%1,%2,%3};" \
                 : "+f"((d)[0]), "+f"((d)[1]), "+f"((d)[2]), "+f"((d)[3]) \
                 : "r"((a)[0]), "r"((a)[1]), "r"((a)[2]), "r"((a)[3]), \
                   "r"(b0), "r"(b1))

// ---------------- SMEM layout (dynamic) ----------------
#define SM_A      0            // 6 slabs x [128 rows x 128B] SW128 = 96KB
#define SM_B0     98304        // [128 x 128B] chunk = 16KB
#define SM_B1     114688
#define SM_SC     131072       // 128 x 132 floats = 67584B (reused for list merge)
#define SM_CS     198656       // 128 floats
#define SMEM_TOTAL 199168

// ============================================================================
// Kernel 0a: fused fp32 -> bf16 split-concat of X + c[j] = ||X_j||^2 - w[j]
//   one warp per row
// ============================================================================
__global__ void convert_x_prep_kernel(const float* __restrict__ X,
                                      const float* __restrict__ w, int n) {
    int row  = (blockIdx.x * blockDim.x + threadIdx.x) >> 5;
    int lane = threadIdx.x & 31;
    if (row >= n) return;
    float4 v = ((const float4*)(X + (size_t)row * D))[lane];
    __nv_bfloat16 hx = __float2bfloat16(v.x), hy = __float2bfloat16(v.y);
    __nv_bfloat16 hz = __float2bfloat16(v.z), hw = __float2bfloat16(v.w);
    __nv_bfloat162 hi0 = __nv_bfloat162(hx, hy);
    __nv_bfloat162 hi1 = __nv_bfloat162(hz, hw);
    __nv_bfloat162 lo0 = __nv_bfloat162(__float2bfloat16(v.x - __bfloat162float(hx)),
                                        __float2bfloat16(v.y - __bfloat162float(hy)));
    __nv_bfloat162 lo1 = __nv_bfloat162(__float2bfloat16(v.z - __bfloat162float(hz)),
                                        __float2bfloat16(v.w - __bfloat162float(hw)));
    size_t b = (size_t)row * KC;
    int c = lane * 4;
    *(__nv_bfloat162*)(g_xc + b + c)           = hi0;
    *(__nv_bfloat162*)(g_xc + b + c + 2)       = hi1;
    *(__nv_bfloat162*)(g_xc + b + 128 + c)     = hi0;     // [hi|hi|lo]
    *(__nv_bfloat162*)(g_xc + b + 128 + c + 2) = hi1;
    *(__nv_bfloat162*)(g_xc + b + 256 + c)     = lo0;
    *(__nv_bfloat162*)(g_xc + b + 256 + c + 2) = lo1;
    float s = v.x * v.x + v.y * v.y + v.z * v.z + v.w * v.w;
    #pragma unroll
    for (int o = 16; o > 0; o >>= 1) s += __shfl_xor_sync(0xffffffffu, s, o);
    if (lane == 0) g_c[row] = s - w[row];
}

// ============================================================================
// Kernel 0b: Q split-concat  [hi|lo|hi]
// ============================================================================
__global__ void convert_q_kernel(const float* __restrict__ Q, int m) {
    int row  = (blockIdx.x * blockDim.x + threadIdx.x) >> 5;
    int lane = threadIdx.x & 31;
    if (row >= m) return;
    float4 v = ((const float4*)(Q + (size_t)row * D))[lane];
    __nv_bfloat16 hx = __float2bfloat16(v.x), hy = __float2bfloat16(v.y);
    __nv_bfloat16 hz = __float2bfloat16(v.z), hw = __float2bfloat16(v.w);
    __nv_bfloat162 hi0 = __nv_bfloat162(hx, hy);
    __nv_bfloat162 hi1 = __nv_bfloat162(hz, hw);
    __nv_bfloat162 lo0 = __nv_bfloat162(__float2bfloat16(v.x - __bfloat162float(hx)),
                                        __float2bfloat16(v.y - __bfloat162float(hy)));
    __nv_bfloat162 lo1 = __nv_bfloat162(__float2bfloat16(v.z - __bfloat162float(hz)),
                                        __float2bfloat16(v.w - __bfloat162float(hw)));
    size_t b = (size_t)row * KC;
    int c = lane * 4;
    *(__nv_bfloat162*)(g_qc + b + c)           = hi0;
    *(__nv_bfloat162*)(g_qc + b + c + 2)       = hi1;
    *(__nv_bfloat162*)(g_qc + b + 128 + c)     = lo0;     // [hi|lo|hi]
    *(__nv_bfloat162*)(g_qc + b + 128 + c + 2) = lo1;
    *(__nv_bfloat162*)(g_qc + b + 256 + c)     = hi0;
    *(__nv_bfloat162*)(g_qc + b + 256 + c + 2) = hi1;
}

// ============================================================================
// Kernel 2: HMMA (mma.sync bf16) GEMM 128q x 128c x 384 + streaming top-10
//   grid = (NCH, m/128), block = 512 (16 warps, 4x4 grid of 32x32 warp tiles)
// ============================================================================
__device__ __forceinline__ void issue_B(uint32_t dst, int jt0, int kc, int j1, int tid) {
    #pragma unroll
    for (int i = 0; i < 2; i++) {
        int seg = tid + 512 * i;            // 0..1023
        int r = seg >> 3, g = seg & 7;
        int j = min(jt0 + r, j1 - 1);
        const void* src = g_xc + (size_t)j * KC + kc * 64 + g * 8;
        uint32_t off = (uint32_t)(r * 128 + g * 16) ^ ((uint32_t)(r & 7) << 4);
        cp16(dst + off, src);
    }
    CP_COMMIT();
}

__global__ void __launch_bounds__(512, 1)
score_kernel(int m, int n)
{
    extern __shared__ char smem[];
    const uint32_t sb = smem_u32(smem);
    const int tid  = threadIdx.x;
    const int lane = tid & 31;
    const int w    = tid >> 5;          // 0..15
    const int qw   = w >> 2;            // 0..3  (query 32-row band)
    const int cw   = w & 3;             // 0..3  (cand 32-col band)
    const int chunk = blockIdx.x, qb = blockIdx.y * 128;

    const int per = (n + NCH - 1) / NCH;
    const int j0  = chunk * per;
    const int j1  = min(n, j0 + per);
    const int ntiles = (j1 - j0 + 127) / 128;

    float* ScF = (float*)(smem + SM_SC);
    float* cs  = (float*)(smem + SM_CS);

    // ---- load resident A: 128 rows x 384 bf16 into 6 SW128 slabs ----
    #pragma unroll
    for (int i = 0; i < 12; i++) {
        int seg = tid + 512 * i;            // 0..6143
        int row = seg / 48, s = seg % 48;
        int gq = min(qb + row, m - 1);
        const void* src = g_qc + (size_t)gq * KC + s * 8;
        uint32_t off = (uint32_t)((s >> 3) * 16384)
                     + (((uint32_t)(row * 128 + (s & 7) * 16)) ^ ((uint32_t)(row & 7) << 4));
        cp16(sb + SM_A + off, src);
    }
    CP_COMMIT();
    issue_B(sb + SM_B0, j0, 0, j1, tid);

    // per-lane ldmatrix base offsets (swizzle masks depend only on row)
    // A: row = qw*32 + mi*16 + (lane&15); khalf = lane>>4
    uint32_t abase[2], amask[2];
    #pragma unroll
    for (int mi = 0; mi < 2; mi++) {
        uint32_t r = (uint32_t)(qw * 32 + mi * 16 + (lane & 15));
        abase[mi] = r * 128 + ((uint32_t)(lane >> 4) << 4);
        amask[mi] = (r & 7) << 4;
    }
    // B: n = cw*32 + ni*16 + (lane&7) + ((lane>>4)<<3); khalf = (lane>>3)&1
    uint32_t bbaseL[2], bmaskL[2];
    #pragma unroll
    for (int ni = 0; ni < 2; ni++) {
        uint32_t nr = (uint32_t)(cw * 32 + ni * 16 + (lane & 7) + ((lane >> 4) << 3));
        bbaseL[ni] = nr * 128 + (((uint32_t)(lane >> 3) & 1) << 4);
        bmaskL[ni] = (nr & 7) << 4;
    }

    float tv[KEEP]; int ti[KEEP];
    #pragma unroll
    for (int k = 0; k < KEEP; k++) { tv[k] = inf_f(); ti[k] = -1; }

    const uint32_t bbuf[2] = { sb + SM_B0, sb + SM_B1 };
    const int q  = tid >> 2;            // scan query (4 threads/query)
    const int hf = tid & 3;

    for (int t = 0; t < ntiles; t++) {
        int jt0 = j0 + t * 128;

        float acc[2][4][4];
        #pragma unroll
        for (int mi = 0; mi < 2; mi++)
            #pragma unroll
            for (int nj = 0; nj < 4; nj++)
                #pragma unroll
                for (int e = 0; e < 4; e++) acc[mi][nj][e] = 0.0f;

        #pragma unroll 1
        for (int kc = 0; kc < 6; kc++) {
            CP_WAIT0();
            __syncthreads();
            if (kc == 0 && tid < 128) {
                int j = jt0 + tid;
                cs[tid] = (j < j1) ? g_c[j] : inf_f();
            }
            if (kc < 5)                 issue_B(bbuf[(kc + 1) & 1], jt0, kc + 1, j1, tid);
            else if (t + 1 < ntiles)    issue_B(sb + SM_B0, jt0 + 128, 0, j1, tid);

            const uint32_t aslab = sb + SM_A + kc * 16384;
            const uint32_t bcur  = bbuf[kc & 1];
            #pragma unroll
            for (int ks = 0; ks < 4; ks++) {
                const uint32_t kb = (uint32_t)(ks * 32);
                uint32_t a0[4], a1[4], b0[4], b1[4];
                LDSM_X4(a0[0], a0[1], a0[2], a0[3], aslab + ((abase[0] + kb) ^ amask[0]));
                LDSM_X4(a1[0], a1[1], a1[2], a1[3], aslab + ((abase[1] + kb) ^ amask[1]));
                LDSM_X4(b0[0], b0[1], b0[2], b0[3], bcur + ((bbaseL[0] + kb) ^ bmaskL[0]));
                LDSM_X4(b1[0], b1[1], b1[2], b1[3], bcur + ((bbaseL[1] + kb) ^ bmaskL[1]));
                MMA16816(acc[0][0], a0, b0[0], b0[1]);
                MMA16816(acc[0][1], a0, b0[2], b0[3]);
                MMA16816(acc[1][0], a1, b0[0], b0[1]);
                MMA16816(acc[1][1], a1, b0[2], b0[3]);
                MMA16816(acc[0][2], a0, b1[0], b1[1]);
                MMA16816(acc[0][3], a0, b1[2], b1[3]);
                MMA16816(acc[1][2], a1, b1[0], b1[1]);
                MMA16816(acc[1][3], a1, b1[2], b1[3]);
            }
        }

        // ---- epilogue: stage scores to smem (stride 132) ----
        {
            int r0 = qw * 32 + (lane >> 2);
            int c0 = cw * 32 + (lane & 3) * 2;
            #pragma unroll
            for (int mi = 0; mi < 2; mi++)
                #pragma unroll
                for (int nj = 0; nj < 4; nj++) {
                    int row = r0 + mi * 16;
                    int col = c0 + nj * 8;
                    ScF[row * 132 + col]           = acc[mi][nj][0];
                    ScF[row * 132 + col + 1]       = acc[mi][nj][1];
                    ScF[(row + 8) * 132 + col]     = acc[mi][nj][2];
                    ScF[(row + 8) * 132 + col + 1] = acc[mi][nj][3];
                }
        }
        __syncthreads();

        // ---- scan: 4 threads per query, 32 cols each, bank-skewed ----
        {
            const float* srow = ScF + q * 132;
            #pragma unroll 4
            for (int jj = 0; jj < 32; jj++) {
                int col = hf * 32 + ((jj + hf) & 31);
                float s = cs[col] - 2.0f * srow[col];
                if (s < tv[KEEP - 1]) {
                    tv[KEEP - 1] = s; ti[KEEP - 1] = jt0 + col;
                    #pragma unroll
                    for (int k = KEEP - 1; k > 0; --k) {
                        if (tv[k] < tv[k - 1]) {
                            float fv = tv[k]; tv[k] = tv[k - 1]; tv[k - 1] = fv;
                            int   iv = ti[k]; ti[k] = ti[k - 1]; ti[k - 1] = iv;
                        }
                    }
                }
            }
        }
        // next iteration's CP_WAIT0 + __syncthreads orders everything
    }

    // ---- merge the four per-query quarter-lists, write partials ----
    __syncthreads();
    float* fvs = (float*)(smem + SM_SC);
    int*   ivs = (int*)(smem + SM_SC + 512 * KEEP * 4);
    #pragma unroll
    for (int k = 0; k < KEEP; k++) { fvs[tid * KEEP + k] = tv[k]; ivs[tid * KEEP + k] = ti[k]; }
    __syncthreads();
    if (tid < 128 && (qb + tid) < m) {
        int p[4] = {0, 0, 0, 0};
        int base = ((qb + tid) * NCH + chunk) * KEEP;
        #pragma unroll
        for (int k = 0; k < KEEP; k++) {
            float bestv = inf_f(); int bl = 0;
            #pragma unroll
            for (int l = 0; l < 4; l++) {
                float v = (p[l] < KEEP) ? fvs[(4 * tid + l) * KEEP + p[l]] : inf_f();
                if (v < bestv) { bestv = v; bl = l; }
            }
            g_pv[base + k] = bestv;
            g_pi[base + k] = ivs[(4 * tid + bl) * KEEP + p[bl]];
            p[bl]++;
        }
    }
}

// ============================================================================
// Kernel 3: merge NCH x 10 partials -> exact top-10 -> rescore -> max act
// ============================================================================
__global__ void __launch_bounds__(128)
merge_kernel(const float* __restrict__ Q, const float* __restrict__ X,
             const float* __restrict__ w, float* __restrict__ out)
{
    __shared__ float sv[NCH * KEEP];
    __shared__ int   si[NCH * KEEP];
    __shared__ float qs[D];
    __shared__ float rv[128];
    __shared__ int   ri[128];
    __shared__ int   s_sel;

    const int q = blockIdx.x, tid = threadIdx.x;

    for (int t = tid; t < NCH * KEEP; t += 128) {
        sv[t] = g_pv[q * NCH * KEEP + t];
        si[t] = g_pi[q * NCH * KEEP + t];
    }
    qs[tid] = Q[(size_t)q * D + tid];
    __syncthreads();

    float best = -inf_f();
    for (int r = 0; r < KEEP; r++) {
        float mv = inf_f(); int mi = -1;
        for (int t = tid; t < NCH * KEEP; t += 128)
            if (sv[t] < mv) { mv = sv[t]; mi = t; }
        rv[tid] = mv; ri[tid] = mi;
        __syncthreads();
        #pragma unroll
        for (int s = 64; s > 0; s >>= 1) {
            if (tid < s && rv[tid + s] < rv[tid]) { rv[tid] = rv[tid + s]; ri[tid] = ri[tid + s]; }
            __syncthreads();
        }
        if (tid == 0) {
            int sel = ri[0];
            s_sel = (sel >= 0 && rv[0] < inf_f()) ? si[sel] : -1;
            if (sel >= 0) sv[sel] = inf_f();
        }
        __syncthreads();
        int idx = s_sel;

        float p = 0.0f;
        if (idx >= 0) {
            float df = X[(size_t)idx * D + tid] - qs[tid];
            p = df * df;
        }
        rv[tid] = p;
        __syncthreads();
        #pragma unroll
        for (int s = 64; s > 0; s >>= 1) {
            if (tid < s) rv[tid] += rv[tid + s];
            __syncthreads();
        }
        if (tid == 0 && idx >= 0) best = fmaxf(best, w[idx] - sqrtf(rv[0]));
        __syncthreads();
    }
    if (tid == 0) out[q] = best;
}

// ============================================================================
// launch
// ============================================================================
extern "C" void kernel_launch(void* const* d_in, const int* in_sizes, int n_in,
                              void* d_out, int out_size)
{
    const float* Xt = (const float*)d_in[0];   // (m, d) queries
    const float* X  = (const float*)d_in[1];   // (n, d) points
    const float* w  = (const float*)d_in[2];   // (n, 1)
    float* out = (float*)d_out;

    int n = in_sizes[2];
    int d = in_sizes[1] / n;
    int m = in_sizes[0] / d;
    (void)n_in; (void)out_size;

    cudaFuncSetAttribute(score_kernel, cudaFuncAttributeMaxDynamicSharedMemorySize, SMEM_TOTAL);

    // 0: fused convert+prep for X; convert for Q   (warp per row)
    convert_x_prep_kernel<<<(n + 7) / 8, 256>>>(X, w, n);
    convert_q_kernel<<<(m + 7) / 8, 256>>>(Xt, m);

    // 2: HMMA GEMM + per-chunk top-10
    dim3 grid(NCH, (m + 127) / 128);
    score_kernel<<<grid, 512, SMEM_TOTAL>>>(m, n);

    // 3: merge + exact rescore + max
    merge_kernel<<<m, 128>>>(Xt, X, w, out);
}